// round 3
// baseline (speedup 1.0000x reference)
#include <cuda_runtime.h>

// LIF membrane recurrence, HBM-bound streaming kernel.
//   mem[t] = 0.25 * mem[t-1] * (1 - spike[t-1]) + x[t] ; spike[t] = mem[t] > 0.5
// x: (8, 32, 128, 32, 32) fp32. 134 MB read + 134 MB write, zero reuse.
// R2: revert R1's .cs hints (regressed: L2 write-buffering is load-bearing).
//     Loads use __ldcg (L2-cached, L1-bypass) to cut L1tex queue pressure;
//     stores are plain (default L2 write-allocate, proven best in R0/R1 A-B).

#define T_STEPS 8
#define INNER   (32 * 128 * 32 * 32)   // 4,194,304 elements per timestep
#define INNER4  (INNER / 4)            // 1,048,576 float4 sites

__global__ void __launch_bounds__(256, 8)
lif_kernel(const float4* __restrict__ x, float4* __restrict__ out) {
    int i = blockIdx.x * blockDim.x + threadIdx.x;   // grid sized exactly, no guard

    // Front-batch all 8 timestep loads (independent -> MLP=8), L1-bypass.
    float4 xv[T_STEPS];
#pragma unroll
    for (int t = 0; t < T_STEPS; ++t) {
        xv[t] = __ldcg(&x[(size_t)t * INNER4 + i]);
    }

    const float DECAY = 0.25f;
    const float THR   = 0.5f;

    float m0 = 0.f, m1 = 0.f, m2 = 0.f, m3 = 0.f;
    float s0 = 0.f, s1 = 0.f, s2 = 0.f, s3 = 0.f;

#pragma unroll
    for (int t = 0; t < T_STEPS; ++t) {
        m0 = DECAY * m0 * (1.0f - s0) + xv[t].x;
        m1 = DECAY * m1 * (1.0f - s1) + xv[t].y;
        m2 = DECAY * m2 * (1.0f - s2) + xv[t].z;
        m3 = DECAY * m3 * (1.0f - s3) + xv[t].w;
        s0 = (m0 > THR) ? 1.0f : 0.0f;
        s1 = (m1 > THR) ? 1.0f : 0.0f;
        s2 = (m2 > THR) ? 1.0f : 0.0f;
        s3 = (m3 > THR) ? 1.0f : 0.0f;
        out[(size_t)t * INNER4 + i] = make_float4(s0, s1, s2, s3);
    }
}

extern "C" void kernel_launch(void* const* d_in, const int* in_sizes, int n_in,
                              void* d_out, int out_size) {
    const float4* x = (const float4*)d_in[0];
    float4* out = (float4*)d_out;
    const int threads = 256;
    const int blocks = INNER4 / threads;   // 4096, exact
    lif_kernel<<<blocks, threads>>>(x, out);
}

// round 4
// speedup vs baseline: 1.1255x; 1.1255x over previous
#include <cuda_runtime.h>

// LIF membrane recurrence:
//   mem[0] = x[0]; spike[0] = mem[0] > 0.5
//   mem[t] = 0.25 * mem[t-1] * (1 - spike[t-1]) + x[t]
//   spike[t] = mem[t] > 0.5
// x: (8, 32, 128, 32, 32) fp32. Recurrence only along t; 4,194,304 independent
// sites. Pure streaming: 134 MB in, 134 MB out -> HBM-bound.
//
// R3: exact revert to R0 (best: 36.6us kernel, DRAM=74%). Both cache-hint
// variants (.cs R1, .cg R2) regressed ~+8.7us — default L1/L2 caching is
// load-bearing for this vectorized stream on sm_103a. Do not re-add hints.

#define T_STEPS 8
#define INNER   (32 * 128 * 32 * 32)   // 4,194,304 elements per timestep
#define INNER4  (INNER / 4)            // float4 granularity

__global__ void lif_kernel(const float4* __restrict__ x, float4* __restrict__ out) {
    int i = blockIdx.x * blockDim.x + threadIdx.x;
    if (i >= INNER4) return;

    // Front-batch all 8 timestep loads (independent -> MLP=8).
    float4 xv[T_STEPS];
#pragma unroll
    for (int t = 0; t < T_STEPS; ++t) {
        xv[t] = x[(size_t)t * INNER4 + i];
    }

    const float DECAY = 0.25f;
    const float THR   = 0.5f;

    float m0 = 0.f, m1 = 0.f, m2 = 0.f, m3 = 0.f;
    float s0 = 0.f, s1 = 0.f, s2 = 0.f, s3 = 0.f;

#pragma unroll
    for (int t = 0; t < T_STEPS; ++t) {
        m0 = DECAY * m0 * (1.0f - s0) + xv[t].x;
        m1 = DECAY * m1 * (1.0f - s1) + xv[t].y;
        m2 = DECAY * m2 * (1.0f - s2) + xv[t].z;
        m3 = DECAY * m3 * (1.0f - s3) + xv[t].w;
        s0 = (m0 > THR) ? 1.0f : 0.0f;
        s1 = (m1 > THR) ? 1.0f : 0.0f;
        s2 = (m2 > THR) ? 1.0f : 0.0f;
        s3 = (m3 > THR) ? 1.0f : 0.0f;
        out[(size_t)t * INNER4 + i] = make_float4(s0, s1, s2, s3);
    }
}

extern "C" void kernel_launch(void* const* d_in, const int* in_sizes, int n_in,
                              void* d_out, int out_size) {
    const float4* x = (const float4*)d_in[0];
    float4* out = (float4*)d_out;
    int threads = 256;
    int blocks = (INNER4 + threads - 1) / threads;   // 4096
    lif_kernel<<<blocks, threads>>>(x, out);
}